// round 17
// baseline (speedup 1.0000x reference)
#include <cuda_runtime.h>
#include <math.h>

#define B      8192
#define H      512
#define V      128
#define STEPS  127
#define R      8       // rows per CTA (3 CTAs/SM)
#define RP     4       // row pairs per CTA
#define NT     256     // threads per CTA

typedef unsigned long long ull;

// ---------------- device scratch ----------------
// W4hh[kk][k][g] = W_hh[g*512+k][kk] ; pad kept for safety
__device__ __align__(16) float g_W4hh[H * H * 4 + 4096];
// W4ih[tok][k][g] = W_ih[g*512+k][tok]
__device__ __align__(16) float g_W4ih[V * H * 4];
// WTcz[kk][k] = W_cz[k][kk]
__device__ float g_WTcz[H * H + 2 * H];
// WTfc[kk][v] = W_fc[v][kk]
__device__ float g_WTfc[H * V + 2 * V];
// b4[k][g] = b_ih[g*512+k] + b_hh[g*512+k]
__device__ __align__(16) float g_b4[H * 4];

// ---------------- f32x2 packed-math helpers ----------------
__device__ __forceinline__ ull pack2(float lo, float hi) {
    ull r; asm("mov.b64 %0, {%1, %2};" : "=l"(r) : "f"(lo), "f"(hi)); return r;
}
__device__ __forceinline__ void unpack2(ull v, float& lo, float& hi) {
    asm("mov.b64 {%0, %1}, %2;" : "=f"(lo), "=f"(hi) : "l"(v));
}
__device__ __forceinline__ ull fma2(ull a, ull b, ull c) {
    ull d; asm("fma.rn.f32x2 %0, %1, %2, %3;" : "=l"(d) : "l"(a), "l"(b), "l"(c)); return d;
}
__device__ __forceinline__ float sigf(float x) { return 1.0f / (1.0f + expf(-x)); }

// ---------------- prep: weight reshuffles ----------------
__global__ void prep_kernel(const float* __restrict__ W_ih, const float* __restrict__ W_hh,
                            const float* __restrict__ b_ih, const float* __restrict__ b_hh,
                            const float* __restrict__ W_cz, const float* __restrict__ W_fc)
{
    int i = blockIdx.x * blockDim.x + threadIdx.x;
    int stride = gridDim.x * blockDim.x;
    for (int idx = i; idx < H * H * 4; idx += stride) {
        int kk = idx >> 11, rem = idx & 2047;
        int k = rem >> 2, g = rem & 3;
        g_W4hh[idx] = W_hh[(g * H + k) * H + kk];
    }
    for (int idx = i; idx < V * H * 4; idx += stride) {
        int t = idx >> 11, rem = idx & 2047;
        int k = rem >> 2, g = rem & 3;
        g_W4ih[idx] = W_ih[(g * H + k) * V + t];
    }
    for (int idx = i; idx < H * H; idx += stride) {
        int kk = idx >> 9, k = idx & 511;
        g_WTcz[idx] = W_cz[k * H + kk];
    }
    for (int idx = i; idx < H * V; idx += stride) {
        int kk = idx >> 7, v = idx & 127;
        g_WTfc[idx] = W_fc[v * H + kk];
    }
    for (int idx = i; idx < H * 4; idx += stride) {
        int k = idx >> 2, g = idx & 3;
        g_b4[idx] = b_ih[g * H + k] + b_hh[g * H + k];
    }
}

// ---------------- main persistent LSTM kernel (3 CTAs/SM) ----------------
__global__ __launch_bounds__(NT, 3)
void lstm_main(const float* __restrict__ z, const float* __restrict__ b_cz,
               const float* __restrict__ b_fc, float* __restrict__ out)
{
    extern __shared__ char smem[];
    float2* shA      = (float2*)smem;                 // RP*H  (h row-pair buffer)
    float2* shB      = shA + RP * H;                  // RP*H
    float*  sh_logit = (float*)(shB + RP * H);        // R*V
    int*    sh_tok   = (int*)(sh_logit + R * V);      // R

    const int tid  = threadIdx.x;
    const int row0 = blockIdx.x * R;

    // ---- load z (= h0) into shA, packed as row pairs ----
    for (int idx = tid; idx < RP * H; idx += NT) {
        int rp = idx >> 9, kk = idx & 511;
        int r0 = row0 + 2 * rp;
        shA[rp * H + kk] = make_float2(z[(size_t)r0 * H + kk],
                                       z[(size_t)(r0 + 1) * H + kk]);
    }
    if (tid < R) sh_tok[tid] = 0;
    __syncthreads();

    // ---- c0 = relu(z @ W_cz^T + b_cz), kept in registers ----
    ull c2[2][RP];
    #pragma unroll
    for (int kp = 0; kp < 2; ++kp) {
        const int k = tid + kp * NT;
        ull a[RP];
        float bz = b_cz[k];
        #pragma unroll
        for (int rp = 0; rp < RP; ++rp) a[rp] = pack2(bz, bz);
        const float* wp = g_WTcz + k;
        const ull* hp = (const ull*)shA;
        for (int kk = 0; kk < H; kk += 2) {
            float w0 = wp[(size_t)kk * H];
            float w1 = wp[(size_t)(kk + 1) * H];
            ull wd0 = pack2(w0, w0), wd1 = pack2(w1, w1);
            #pragma unroll
            for (int rp = 0; rp < RP; ++rp) {
                ulonglong2 h2 = *(const ulonglong2*)&hp[rp * H + kk];   // LDS.128
                a[rp] = fma2(h2.x, wd0, a[rp]);
                a[rp] = fma2(h2.y, wd1, a[rp]);
            }
        }
        #pragma unroll
        for (int rp = 0; rp < RP; ++rp) {
            float x0, x1; unpack2(a[rp], x0, x1);
            c2[kp][rp] = pack2(fmaxf(x0, 0.f), fmaxf(x1, 0.f));
        }
    }

    const float4* W4hh = (const float4*)g_W4hh;
    const float4* W4ih = (const float4*)g_W4ih;
    const float4* b4p  = (const float4*)g_b4;

    for (int step = 0; step < STEPS; ++step) {
        float2* hc = (step & 1) ? shB : shA;
        float2* hn = (step & 1) ? shA : shB;
        const ull* hp = (const ull*)hc;
        ull* ho = (ull*)hn;

        // ---- gates + state update ----
        #pragma unroll
        for (int kp = 0; kp < 2; ++kp) {
            const int k = tid + kp * NT;
            float4 bb = b4p[k];
            ull a0[RP], a1[RP], a2[RP], a3[RP];
            #pragma unroll
            for (int rp = 0; rp < RP; ++rp) {
                float4 wi0 = W4ih[sh_tok[2 * rp] * H + k];
                float4 wi1 = W4ih[sh_tok[2 * rp + 1] * H + k];
                a0[rp] = pack2(bb.x + wi0.x, bb.x + wi1.x);
                a1[rp] = pack2(bb.y + wi0.y, bb.y + wi1.y);
                a2[rp] = pack2(bb.z + wi0.z, bb.z + wi1.z);
                a3[rp] = pack2(bb.w + wi0.w, bb.w + wi1.w);
            }
            const float4* wp = W4hh + k;
            for (int kk = 0; kk < H; kk += 2) {
                float4 w0 = wp[(size_t)kk * H];
                float4 w1 = wp[(size_t)(kk + 1) * H];
                ull wx0 = pack2(w0.x, w0.x), wy0 = pack2(w0.y, w0.y);
                ull wz0 = pack2(w0.z, w0.z), ww0 = pack2(w0.w, w0.w);
                ull wx1 = pack2(w1.x, w1.x), wy1 = pack2(w1.y, w1.y);
                ull wz1 = pack2(w1.z, w1.z), ww1 = pack2(w1.w, w1.w);
                #pragma unroll
                for (int rp = 0; rp < RP; ++rp) {
                    ulonglong2 h2 = *(const ulonglong2*)&hp[rp * H + kk];   // LDS.128
                    a0[rp] = fma2(h2.x, wx0, a0[rp]);
                    a1[rp] = fma2(h2.x, wy0, a1[rp]);
                    a2[rp] = fma2(h2.x, wz0, a2[rp]);
                    a3[rp] = fma2(h2.x, ww0, a3[rp]);
                    a0[rp] = fma2(h2.y, wx1, a0[rp]);
                    a1[rp] = fma2(h2.y, wy1, a1[rp]);
                    a2[rp] = fma2(h2.y, wz1, a2[rp]);
                    a3[rp] = fma2(h2.y, ww1, a3[rp]);
                }
            }
            #pragma unroll
            for (int rp = 0; rp < RP; ++rp) {
                float i0, i1, f0, f1, g0, g1, o0, o1, cc0, cc1;
                unpack2(a0[rp], i0, i1);
                unpack2(a1[rp], f0, f1);
                unpack2(a2[rp], g0, g1);
                unpack2(a3[rp], o0, o1);
                unpack2(c2[kp][rp], cc0, cc1);
                float cn0 = sigf(f0) * cc0 + sigf(i0) * tanhf(g0);
                float cn1 = sigf(f1) * cc1 + sigf(i1) * tanhf(g1);
                float h0v = sigf(o0) * tanhf(cn0);
                float h1v = sigf(o1) * tanhf(cn1);
                c2[kp][rp] = pack2(cn0, cn1);
                ho[rp * H + k] = pack2(h0v, h1v);
            }
        }
        __syncthreads();

        // ---- fc: logits = relu(h_new @ W_fc^T + b_fc) ----
        {
            const int v  = tid & (V - 1);
            const int rh = tid >> 7;          // 0 or 1: row-half
            const int p0 = rh * 2;            // rh0: pairs 0..1, rh1: pairs 2..3
            ull fa[2];
            float bv = b_fc[v];
            fa[0] = pack2(bv, bv);
            fa[1] = pack2(bv, bv);
            const float* wf = g_WTfc + v;
            const ull* hpn = (const ull*)hn + (size_t)p0 * H;
            for (int kk = 0; kk < H; kk += 2) {
                float w0 = wf[(size_t)kk * V];
                float w1 = wf[(size_t)(kk + 1) * V];
                ull wd0 = pack2(w0, w0), wd1 = pack2(w1, w1);
                #pragma unroll
                for (int p = 0; p < 2; ++p) {
                    ulonglong2 h2 = *(const ulonglong2*)&hpn[p * H + kk];   // LDS.128
                    fa[p] = fma2(h2.x, wd0, fa[p]);
                    fa[p] = fma2(h2.y, wd1, fa[p]);
                }
            }
            #pragma unroll
            for (int p = 0; p < 2; ++p) {
                float l0, l1; unpack2(fa[p], l0, l1);
                l0 = fmaxf(l0, 0.f); l1 = fmaxf(l1, 0.f);
                int r0 = (p0 + p) * 2;
                sh_logit[r0 * V + v]       = l0;
                sh_logit[(r0 + 1) * V + v] = l1;
                int gr0 = row0 + r0;
                out[((size_t)gr0 * STEPS + step) * V + v]       = l0;
                out[((size_t)(gr0 + 1) * STEPS + step) * V + v] = l1;
            }
        }
        __syncthreads();

        // ---- greedy argmax per row (lowest index wins ties) ----
        {
            const int wid = tid >> 5, lane = tid & 31;
            if (wid < R) {
                float best = -1.f; int bi = 0;
                #pragma unroll
                for (int q = 0; q < 4; ++q) {
                    int vv = lane + 32 * q;
                    float val = sh_logit[wid * V + vv];
                    if (val > best) { best = val; bi = vv; }
                }
                #pragma unroll
                for (int off = 16; off; off >>= 1) {
                    float ov = __shfl_xor_sync(0xffffffffu, best, off);
                    int   oi = __shfl_xor_sync(0xffffffffu, bi, off);
                    if (ov > best || (ov == best && oi < bi)) { best = ov; bi = oi; }
                }
                if (lane == 0) sh_tok[wid] = bi;
            }
        }
        __syncthreads();
    }
}

// ---------------- launch ----------------
extern "C" void kernel_launch(void* const* d_in, const int* in_sizes, int n_in,
                              void* d_out, int out_size)
{
    const float* z    = (const float*)d_in[0];
    const float* W_ih = (const float*)d_in[1];
    const float* W_hh = (const float*)d_in[2];
    const float* b_ih = (const float*)d_in[3];
    const float* b_hh = (const float*)d_in[4];
    const float* W_cz = (const float*)d_in[5];
    const float* b_cz = (const float*)d_in[6];
    const float* W_fc = (const float*)d_in[7];
    const float* b_fc = (const float*)d_in[8];
    float* out = (float*)d_out;

    prep_kernel<<<1024, 256>>>(W_ih, W_hh, b_ih, b_hh, W_cz, W_fc);

    const int smem_bytes = 2 * RP * H * (int)sizeof(float2)    // h double buffer (32 KB)
                         + R * V * (int)sizeof(float)          // logits (4 KB)
                         + R * (int)sizeof(int);               // tokens
    cudaFuncSetAttribute(lstm_main, cudaFuncAttributeMaxDynamicSharedMemorySize, smem_bytes);
    lstm_main<<<B / R, NT, smem_bytes>>>(z, b_cz, b_fc, out);
}